// round 5
// baseline (speedup 1.0000x reference)
#include <cuda_runtime.h>
#include <math.h>

#define CH 64
#define MAX_NODES 50000
#define NPB 128       // nodes per GEMM tile
#define ASTR 129      // A tile stride (words)
#define WSTR 65       // W tile stride (words)
// K=64 GEMM tile smem: A 64x129 + W 64x65 floats = 49664 bytes
#define GEMM_SMEM ((64 * ASTR + 64 * WSTR) * (int)sizeof(float))

// Scratch for the scatter-accumulated, scaled source features.
__device__ float g_buf[MAX_NODES * CH];
// 1 if edge_index buffer is int64, 0 if int32 (probed on device each run).
__device__ int g_is64;

// ---------------------------------------------------------------------------
// Kernel 1: zero the scratch accumulator + probe edge_index dtype.
// int64 little-endian with values < 2^31 => every odd 32-bit word zero;
// random int32 indices can't produce 32 zeros.
// ---------------------------------------------------------------------------
__global__ void zero_probe_kernel(int n4, const int* __restrict__ ei32) {
    int i = blockIdx.x * blockDim.x + threadIdx.x;
    if (i < n4) {
        reinterpret_cast<float4*>(g_buf)[i] = make_float4(0.f, 0.f, 0.f, 0.f);
    }
    if (blockIdx.x == 0 && threadIdx.x == 0) {
        int is64 = 1;
        #pragma unroll 1
        for (int j = 0; j < 32; j++) {
            if (ei32[2 * j + 1] != 0) { is64 = 0; break; }
        }
        g_is64 = is64;
    }
}

// ---------------------------------------------------------------------------
// GEMM tile body (K=64): out_tile(128 nodes x 64 outputs) = A_tile @ W^T
// A source row-major [n][64], W row-major [o][64]. 256 threads.
// Per thread: 4 nodes (tn + 32j) x 8 outputs. If ACCUM, out += result.
// ---------------------------------------------------------------------------
template <bool ACCUM>
__device__ __forceinline__ void gemm_tile(
    float* __restrict__ smem,
    const float* __restrict__ A,
    const float* __restrict__ W,
    float* __restrict__ out,
    int node0, int N)
{
    float* As = smem;               // As[k * ASTR + n], k<64
    float* Ws = smem + 64 * ASTR;   // Ws[k * WSTR + o], k<64
    int tid = threadIdx.x;

    // Stage W: coalesced LDG, transposed STS.
    for (int idx = tid; idx < CH * CH; idx += 256) {
        int o = idx >> 6;
        int k = idx & 63;
        Ws[k * WSTR + o] = __ldg(&W[o * CH + k]);
    }

    // Stage A: float4 LDG, scalar STS transpose into [k][n].
    for (int idx4 = tid; idx4 < NPB * 16; idx4 += 256) {
        int n  = idx4 >> 4;
        int i4 = idx4 & 15;
        int gn = node0 + n;
        float4 v = make_float4(0.f, 0.f, 0.f, 0.f);
        if (gn < N) {
            v = __ldg(reinterpret_cast<const float4*>(A + (size_t)gn * CH) + i4);
        }
        int k = i4 * 4;
        As[(k + 0) * ASTR + n] = v.x;
        As[(k + 1) * ASTR + n] = v.y;
        As[(k + 2) * ASTR + n] = v.z;
        As[(k + 3) * ASTR + n] = v.w;
    }
    __syncthreads();

    int tn = tid & 31;
    int ob = (tid >> 5) * 8;

    float acc[4][8];
    #pragma unroll
    for (int j = 0; j < 4; j++)
        #pragma unroll
        for (int o = 0; o < 8; o++) acc[j][o] = 0.f;

    #pragma unroll 4
    for (int k = 0; k < 64; k++) {
        const float* ar = As + k * ASTR + tn;
        const float* wr = Ws + k * WSTR + ob;
        float a[4], w[8];
        #pragma unroll
        for (int j = 0; j < 4; j++) a[j] = ar[32 * j];
        #pragma unroll
        for (int o = 0; o < 8; o++) w[o] = wr[o];
        #pragma unroll
        for (int j = 0; j < 4; j++)
            #pragma unroll
            for (int o = 0; o < 8; o++)
                acc[j][o] += a[j] * w[o];
    }

    #pragma unroll
    for (int j = 0; j < 4; j++) {
        int gn = node0 + tn + 32 * j;
        if (gn < N) {
            float4* orow = reinterpret_cast<float4*>(out + (size_t)gn * CH + ob);
            float4 r0 = make_float4(acc[j][0], acc[j][1], acc[j][2], acc[j][3]);
            float4 r1 = make_float4(acc[j][4], acc[j][5], acc[j][6], acc[j][7]);
            if (ACCUM) {
                float4 p0 = orow[0], p1 = orow[1];
                r0.x += p0.x; r0.y += p0.y; r0.z += p0.z; r0.w += p0.w;
                r1.x += p1.x; r1.y += p1.y; r1.z += p1.z; r1.w += p1.w;
            }
            orow[0] = r0;
            orow[1] = r1;
        }
    }
}

// ---------------------------------------------------------------------------
// Kernel 2 (fused): blocks [0, ngemm) compute out = x @ psi^T (independent of
// scatter); blocks [ngemm, ...) do the edge scatter
//   g_buf[dst] += ||edge_attr[e]|| * x[src]
// (16 threads/edge, float4 lanes, leader loads metadata).
// GEMM blocks come first so they start in wave 1 and hide under the scatter.
// ---------------------------------------------------------------------------
extern __shared__ float smem_dyn[];

__global__ void __launch_bounds__(256, 4) fused_psi_scatter_kernel(
    const float* __restrict__ x,
    const void* __restrict__ ei_raw,
    const float* __restrict__ ea,
    const float* __restrict__ psi,
    float* __restrict__ out,
    int E, int N, int ngemm)
{
    if ((int)blockIdx.x < ngemm) {
        gemm_tile<false>(smem_dyn, x, psi, out, blockIdx.x * NPB, N);
        return;
    }

    int e = (blockIdx.x - ngemm) * 16 + (threadIdx.x >> 4);
    if (e >= E) return;
    int lane = threadIdx.x & 15;
    int grpleader = threadIdx.x & 16;

    int src = 0, dst = 0;
    float scale = 0.f;
    if (lane == 0) {
        if (g_is64) {
            const long long* ei = (const long long*)ei_raw;
            src = (int)__ldg(&ei[e]);
            dst = (int)__ldg(&ei[E + e]);
        } else {
            const int* ei = (const int*)ei_raw;
            src = __ldg(&ei[e]);
            dst = __ldg(&ei[E + e]);
        }
        float a0 = __ldg(&ea[3 * e + 0]);
        float a1 = __ldg(&ea[3 * e + 1]);
        float a2 = __ldg(&ea[3 * e + 2]);
        scale = sqrtf(a0 * a0 + a1 * a1 + a2 * a2);
    }
    src   = __shfl_sync(0xffffffffu, src,   grpleader);
    dst   = __shfl_sync(0xffffffffu, dst,   grpleader);
    scale = __shfl_sync(0xffffffffu, scale, grpleader);

    if ((unsigned)src >= (unsigned)N || (unsigned)dst >= (unsigned)N) return;

    float4 v = __ldg(reinterpret_cast<const float4*>(x + (size_t)src * CH) + lane);
    v.x *= scale; v.y *= scale; v.z *= scale; v.w *= scale;

    float* addr = g_buf + (size_t)dst * CH + lane * 4;
    asm volatile("red.global.add.v4.f32 [%0], {%1, %2, %3, %4};"
                 :: "l"(addr), "f"(v.x), "f"(v.y), "f"(v.z), "f"(v.w)
                 : "memory");
}

// ---------------------------------------------------------------------------
// Kernel 3: out += g_buf @ phi^T   (K=64 GEMM, accumulate into out)
// ---------------------------------------------------------------------------
__global__ void __launch_bounds__(256, 4) phi_gemm_kernel(
    const float* __restrict__ phi,
    float* __restrict__ out,
    int N)
{
    gemm_tile<true>(smem_dyn, g_buf, phi, out, blockIdx.x * NPB, N);
}

// ---------------------------------------------------------------------------
// Launch
// ---------------------------------------------------------------------------
extern "C" void kernel_launch(void* const* d_in, const int* in_sizes, int n_in,
                              void* d_out, int out_size) {
    const float* x   = (const float*)d_in[0];
    const void*  ei  = d_in[1];
    const float* ea  = (const float*)d_in[2];
    const float* phi = (const float*)d_in[3];
    const float* psi = (const float*)d_in[4];
    float*       out = (float*)d_out;

    int N = in_sizes[0] / CH;   // 50000
    int E = in_sizes[1] / 2;    // 800000

    // 1. zero accumulator + probe dtype
    int n4 = (N * CH) / 4;
    zero_probe_kernel<<<(n4 + 255) / 256, 256>>>(n4, (const int*)ei);

    // 2. fused: psi-GEMM (391 blocks) + edge scatter (50000 blocks)
    int ngemm = (N + NPB - 1) / NPB;
    int nscat = (E + 15) / 16;
    cudaFuncSetAttribute(fused_psi_scatter_kernel,
                         cudaFuncAttributeMaxDynamicSharedMemorySize, GEMM_SMEM);
    fused_psi_scatter_kernel<<<ngemm + nscat, 256, GEMM_SMEM>>>(
        x, ei, ea, psi, out, E, N, ngemm);

    // 3. out += phi(g_buf)
    cudaFuncSetAttribute(phi_gemm_kernel,
                         cudaFuncAttributeMaxDynamicSharedMemorySize, GEMM_SMEM);
    phi_gemm_kernel<<<ngemm, 256, GEMM_SMEM>>>(phi, out, N);
}

// round 6
// speedup vs baseline: 1.0991x; 1.0991x over previous
#include <cuda_runtime.h>
#include <math.h>

#define CH 64
#define MAX_NODES 50000

// Scratch for the scatter-accumulated, scaled source features.
__device__ float g_buf[MAX_NODES * CH];
// 1 if edge_index buffer is int64, 0 if int32 (probed on device each run).
__device__ int g_is64;

// ---------------------------------------------------------------------------
// Kernel 1: zero the scratch accumulator + probe edge_index dtype.
// int64 little-endian with values < 2^31 => every odd 32-bit word zero;
// random int32 indices can't produce 32 consecutive zeros there.
// ---------------------------------------------------------------------------
__global__ void zero_probe_kernel(int n4, const int* __restrict__ ei32) {
    int i = blockIdx.x * blockDim.x + threadIdx.x;
    if (i < n4) {
        reinterpret_cast<float4*>(g_buf)[i] = make_float4(0.f, 0.f, 0.f, 0.f);
    }
    if (blockIdx.x == 0 && threadIdx.x == 0) {
        int is64 = 1;
        #pragma unroll 1
        for (int j = 0; j < 32; j++) {
            if (ei32[2 * j + 1] != 0) { is64 = 0; break; }
        }
        g_is64 = is64;
    }
}

// ---------------------------------------------------------------------------
// Kernel 2: edge scatter.  g_buf[dst] += ||edge_attr[e]|| * x[src]
// 16 threads per edge, one float4 per thread; leader loads metadata.
// No smem -> occupancy unconstrained; L2/LTS-bound.
// ---------------------------------------------------------------------------
__global__ void __launch_bounds__(256) edge_scatter_kernel(
    const float* __restrict__ x,
    const void* __restrict__ ei_raw,
    const float* __restrict__ ea,
    int E, int N)
{
    int t = blockIdx.x * blockDim.x + threadIdx.x;
    int e = t >> 4;
    if (e >= E) return;
    int lane = threadIdx.x & 15;
    int grpleader = threadIdx.x & 16;

    int src = 0, dst = 0;
    float scale = 0.f;
    if (lane == 0) {
        if (g_is64) {
            const long long* ei = (const long long*)ei_raw;
            src = (int)__ldg(&ei[e]);
            dst = (int)__ldg(&ei[E + e]);
        } else {
            const int* ei = (const int*)ei_raw;
            src = __ldg(&ei[e]);
            dst = __ldg(&ei[E + e]);
        }
        float a0 = __ldg(&ea[3 * e + 0]);
        float a1 = __ldg(&ea[3 * e + 1]);
        float a2 = __ldg(&ea[3 * e + 2]);
        scale = sqrtf(a0 * a0 + a1 * a1 + a2 * a2);
    }
    src   = __shfl_sync(0xffffffffu, src,   grpleader);
    dst   = __shfl_sync(0xffffffffu, dst,   grpleader);
    scale = __shfl_sync(0xffffffffu, scale, grpleader);

    if ((unsigned)src >= (unsigned)N || (unsigned)dst >= (unsigned)N) return;

    float4 v = __ldg(reinterpret_cast<const float4*>(x + (size_t)src * CH) + lane);
    v.x *= scale; v.y *= scale; v.z *= scale; v.w *= scale;

    float* addr = g_buf + (size_t)dst * CH + lane * 4;
    asm volatile("red.global.add.v4.f32 [%0], {%1, %2, %3, %4};"
                 :: "l"(addr), "f"(v.x), "f"(v.y), "f"(v.z), "f"(v.w)
                 : "memory");
}

// ---------------------------------------------------------------------------
// Kernel 3: fused GEMM   out = [x | g_buf] @ [psi ; phi]^T
// One node per thread, 64 accumulators. W in smem row-major [o][0..127]
// (row o = [psi_o | phi_o]); inner reads are lane-uniform LDS.128 broadcasts.
// ---------------------------------------------------------------------------
__global__ void __launch_bounds__(256, 2) fused_gemm_kernel(
    const float* __restrict__ x,
    const float* __restrict__ phi,
    const float* __restrict__ psi,
    float* __restrict__ out,
    int N)
{
    __shared__ float4 Ws4[CH * 32];   // Ws4[o * 32 + c], c = k-chunk of 4; 32 KB
    int tid = threadIdx.x;

    // Stage W: row o = [psi[o][:] | phi[o][:]], coalesced float4 copy.
    const float4* psi4 = reinterpret_cast<const float4*>(psi);
    const float4* phi4 = reinterpret_cast<const float4*>(phi);
    for (int idx = tid; idx < CH * 32; idx += 256) {
        int o = idx >> 5;
        int j = idx & 31;
        Ws4[o * 32 + j] = (j < 16) ? __ldg(psi4 + o * 16 + j)
                                   : __ldg(phi4 + o * 16 + (j - 16));
    }
    __syncthreads();

    int n = blockIdx.x * 256 + tid;
    if (n >= N) return;

    const float4* xr = reinterpret_cast<const float4*>(x + (size_t)n * CH);
    const float4* br = reinterpret_cast<const float4*>(g_buf + (size_t)n * CH);

    float acc[CH];
    #pragma unroll
    for (int o = 0; o < CH; o++) acc[o] = 0.f;

    // First half: A = x, chunks c = 0..15
    #pragma unroll 2
    for (int c = 0; c < 16; c++) {
        float4 a = __ldg(xr + c);
        const float4* wcol = Ws4 + c;
        #pragma unroll
        for (int o = 0; o < CH; o++) {
            float4 w = wcol[o * 32];     // lane-uniform -> broadcast
            acc[o] += a.x * w.x + a.y * w.y + a.z * w.z + a.w * w.w;
        }
    }
    // Second half: A = g_buf, chunks c = 16..31
    #pragma unroll 2
    for (int c = 0; c < 16; c++) {
        float4 a = br[c];
        const float4* wcol = Ws4 + 16 + c;
        #pragma unroll
        for (int o = 0; o < CH; o++) {
            float4 w = wcol[o * 32];
            acc[o] += a.x * w.x + a.y * w.y + a.z * w.z + a.w * w.w;
        }
    }

    float4* orow = reinterpret_cast<float4*>(out + (size_t)n * CH);
    #pragma unroll
    for (int o4 = 0; o4 < 16; o4++) {
        orow[o4] = make_float4(acc[4 * o4 + 0], acc[4 * o4 + 1],
                               acc[4 * o4 + 2], acc[4 * o4 + 3]);
    }
}

// ---------------------------------------------------------------------------
// Launch
// ---------------------------------------------------------------------------
extern "C" void kernel_launch(void* const* d_in, const int* in_sizes, int n_in,
                              void* d_out, int out_size) {
    const float* x   = (const float*)d_in[0];
    const void*  ei  = d_in[1];
    const float* ea  = (const float*)d_in[2];
    const float* phi = (const float*)d_in[3];
    const float* psi = (const float*)d_in[4];
    float*       out = (float*)d_out;

    int N = in_sizes[0] / CH;   // 50000
    int E = in_sizes[1] / 2;    // 800000

    // 1. zero accumulator + probe dtype
    int n4 = (N * CH) / 4;
    zero_probe_kernel<<<(n4 + 255) / 256, 256>>>(n4, (const int*)ei);

    // 2. edge scatter (16 threads per edge)
    long long tot = (long long)E * 16;
    int eblocks = (int)((tot + 255) / 256);
    edge_scatter_kernel<<<eblocks, 256>>>(x, ei, ea, E, N);

    // 3. fused GEMM: out = [x | g_buf] @ [psi ; phi]^T
    fused_gemm_kernel<<<(N + 255) / 256, 256>>>(x, phi, psi, out, N);
}

// round 8
// speedup vs baseline: 1.1911x; 1.0837x over previous
#include <cuda_runtime.h>
#include <math.h>

#define CH 64
#define MAX_NODES 50000
#define KS 128        // concat K dim: [x | g_buf]
#define NPB 128       // nodes per GEMM tile
#define ASTR 132      // A tile row stride in floats (mult of 4 -> aligned LDS.128)
#define WSTR 68       // W tile row stride in floats (mult of 4)
#define GEMM_SMEM ((KS * ASTR + KS * WSTR) * (int)sizeof(float))  // 102400 B

// Scratch for the scatter-accumulated, scaled source features.
__device__ float g_buf[MAX_NODES * CH];
// 1 if edge_index buffer is int64, 0 if int32 (probed on device each run).
__device__ int g_is64;

// ---------------------------------------------------------------------------
// Kernel 1: zero the scratch accumulator + probe edge_index dtype.
// int64 little-endian with values < 2^31 => every odd 32-bit word zero;
// random int32 indices can't produce 32 consecutive zeros there.
// ---------------------------------------------------------------------------
__global__ void zero_probe_kernel(int n4, const int* __restrict__ ei32) {
    int i = blockIdx.x * blockDim.x + threadIdx.x;
    if (i < n4) {
        reinterpret_cast<float4*>(g_buf)[i] = make_float4(0.f, 0.f, 0.f, 0.f);
    }
    if (blockIdx.x == 0 && threadIdx.x == 0) {
        int is64 = 1;
        #pragma unroll 1
        for (int j = 0; j < 32; j++) {
            if (ei32[2 * j + 1] != 0) { is64 = 0; break; }
        }
        g_is64 = is64;
    }
}

// ---------------------------------------------------------------------------
// Kernel 2: edge scatter.  g_buf[dst] += ||edge_attr[e]|| * x[src]
// 16 threads per edge, one float4 per thread; leader loads metadata.
// ---------------------------------------------------------------------------
__global__ void __launch_bounds__(256) edge_scatter_kernel(
    const float* __restrict__ x,
    const void* __restrict__ ei_raw,
    const float* __restrict__ ea,
    int E, int N)
{
    int t = blockIdx.x * blockDim.x + threadIdx.x;
    int e = t >> 4;
    if (e >= E) return;
    int lane = threadIdx.x & 15;
    int grpleader = threadIdx.x & 16;

    int src = 0, dst = 0;
    float scale = 0.f;
    if (lane == 0) {
        if (g_is64) {
            const long long* ei = (const long long*)ei_raw;
            src = (int)__ldg(&ei[e]);
            dst = (int)__ldg(&ei[E + e]);
        } else {
            const int* ei = (const int*)ei_raw;
            src = __ldg(&ei[e]);
            dst = __ldg(&ei[E + e]);
        }
        float a0 = __ldg(&ea[3 * e + 0]);
        float a1 = __ldg(&ea[3 * e + 1]);
        float a2 = __ldg(&ea[3 * e + 2]);
        scale = sqrtf(a0 * a0 + a1 * a1 + a2 * a2);
    }
    src   = __shfl_sync(0xffffffffu, src,   grpleader);
    dst   = __shfl_sync(0xffffffffu, dst,   grpleader);
    scale = __shfl_sync(0xffffffffu, scale, grpleader);

    if ((unsigned)src >= (unsigned)N || (unsigned)dst >= (unsigned)N) return;

    float4 v = __ldg(reinterpret_cast<const float4*>(x + (size_t)src * CH) + lane);
    v.x *= scale; v.y *= scale; v.z *= scale; v.w *= scale;

    float* addr = g_buf + (size_t)dst * CH + lane * 4;
    asm volatile("red.global.add.v4.f32 [%0], {%1, %2, %3, %4};"
                 :: "l"(addr), "f"(v.x), "f"(v.y), "f"(v.z), "f"(v.w)
                 : "memory");
}

// ---------------------------------------------------------------------------
// Kernel 3: fused GEMM   out = [x | g_buf] @ [psi ; phi]^T
// Tile: 128 nodes x 64 outputs x K=128. 256 threads.
// Per thread: 4 CONSECUTIVE nodes (nb=4*tn) x 8 outputs -> 32 accumulators.
// Per k-step: 1 aligned LDS.128 (A, conflict-free) + 2 warp-uniform LDS.128
// (W, broadcast) + 32 FFMA.
// ---------------------------------------------------------------------------
extern __shared__ float smem[];

__global__ void __launch_bounds__(256, 2) fused_gemm_kernel(
    const float* __restrict__ x,
    const float* __restrict__ phi,
    const float* __restrict__ psi,
    float* __restrict__ out,
    int N)
{
    float* As = smem;                 // As[k * ASTR + n]
    float* Ws = smem + KS * ASTR;     // Ws[k * WSTR + o]
    int tid = threadIdx.x;
    int node0 = blockIdx.x * NPB;

    // Stage W: Ws[k][o] = [psi;phi][o][k]. o fast across lanes -> STS banks
    // lane+const (conflict-free). Global: 4B per lane at 256B stride (L2-hit).
    for (int idx = tid; idx < CH * KS; idx += 256) {
        int o = idx & 63;
        int i = idx >> 6;
        float v = (i < CH) ? __ldg(&psi[o * CH + i])
                           : __ldg(&phi[o * CH + (i - CH)]);
        Ws[i * WSTR + o] = v;
    }

    // Stage A transpose: n fast across lanes -> each of the 4 STS has banks
    // lane+const (conflict-free). Global: 16B per lane at 256B stride.
    for (int idx4 = tid; idx4 < NPB * 32; idx4 += 256) {
        int n  = idx4 & 127;       // node within tile (lane-consecutive)
        int i4 = idx4 >> 7;        // which float4 of the 128-float concat row
        int gn = node0 + n;
        float4 v = make_float4(0.f, 0.f, 0.f, 0.f);
        if (gn < N) {
            v = (i4 < 16)
                ? __ldg(reinterpret_cast<const float4*>(x + (size_t)gn * CH) + i4)
                : __ldg(reinterpret_cast<const float4*>(g_buf + (size_t)gn * CH) + (i4 - 16));
        }
        int i = i4 * 4;
        As[(i + 0) * ASTR + n] = v.x;
        As[(i + 1) * ASTR + n] = v.y;
        As[(i + 2) * ASTR + n] = v.z;
        As[(i + 3) * ASTR + n] = v.w;
    }
    __syncthreads();

    int tn = tid & 31;          // lane
    int nb = tn * 4;            // 4 consecutive nodes
    int ob = (tid >> 5) * 8;    // 8 consecutive outputs (warp-uniform)

    float acc[4][8];
    #pragma unroll
    for (int j = 0; j < 4; j++)
        #pragma unroll
        for (int o = 0; o < 8; o++) acc[j][o] = 0.f;

    #pragma unroll 4
    for (int k = 0; k < KS; k++) {
        float4 a4 = *reinterpret_cast<const float4*>(As + k * ASTR + nb);
        const float4* wr = reinterpret_cast<const float4*>(Ws + k * WSTR + ob);
        float4 w0 = wr[0];
        float4 w1 = wr[1];
        float a[4] = {a4.x, a4.y, a4.z, a4.w};
        float w[8] = {w0.x, w0.y, w0.z, w0.w, w1.x, w1.y, w1.z, w1.w};
        #pragma unroll
        for (int j = 0; j < 4; j++)
            #pragma unroll
            for (int o = 0; o < 8; o++)
                acc[j][o] += a[j] * w[o];
    }

    // Output: 4 consecutive node rows x 8 floats -> 2 STG.128 each; warp
    // covers an 8KB contiguous block.
    #pragma unroll
    for (int j = 0; j < 4; j++) {
        int gn = node0 + nb + j;
        if (gn < N) {
            float4* orow = reinterpret_cast<float4*>(out + (size_t)gn * CH + ob);
            orow[0] = make_float4(acc[j][0], acc[j][1], acc[j][2], acc[j][3]);
            orow[1] = make_float4(acc[j][4], acc[j][5], acc[j][6], acc[j][7]);
        }
    }
}

// ---------------------------------------------------------------------------
// Launch
// ---------------------------------------------------------------------------
extern "C" void kernel_launch(void* const* d_in, const int* in_sizes, int n_in,
                              void* d_out, int out_size) {
    const float* x   = (const float*)d_in[0];
    const void*  ei  = d_in[1];
    const float* ea  = (const float*)d_in[2];
    const float* phi = (const float*)d_in[3];
    const float* psi = (const float*)d_in[4];
    float*       out = (float*)d_out;

    int N = in_sizes[0] / CH;   // 50000
    int E = in_sizes[1] / 2;    // 800000

    // 1. zero accumulator + probe dtype
    int n4 = (N * CH) / 4;
    zero_probe_kernel<<<(n4 + 255) / 256, 256>>>(n4, (const int*)ei);

    // 2. edge scatter (16 threads per edge)
    long long tot = (long long)E * 16;
    int eblocks = (int)((tot + 255) / 256);
    edge_scatter_kernel<<<eblocks, 256>>>(x, ei, ea, E, N);

    // 3. fused GEMM: out = [x | g_buf] @ [psi ; phi]^T
    cudaFuncSetAttribute(fused_gemm_kernel,
                         cudaFuncAttributeMaxDynamicSharedMemorySize,
                         GEMM_SMEM);
    fused_gemm_kernel<<<(N + NPB - 1) / NPB, 256, GEMM_SMEM>>>(x, phi, psi, out, N);
}

// round 9
// speedup vs baseline: 1.2034x; 1.0103x over previous
#include <cuda_runtime.h>
#include <math.h>

#define CH 64
#define MAX_NODES 50000
#define KS 128        // concat K dim: [x | g_buf]
#define NPB 128       // nodes per GEMM tile
#define ASTR 132      // A tile row stride in floats (mult of 4 -> aligned LDS.128)
#define WSTR 68       // W tile row stride in floats (mult of 4)
#define GEMM_SMEM ((KS * ASTR + KS * WSTR) * (int)sizeof(float))  // 102400 B

// Scratch for the scatter-accumulated, scaled source features.
__device__ float g_buf[MAX_NODES * CH];
// 1 if edge_index buffer is int64, 0 if int32 (probed on device each run).
__device__ int g_is64;

// ---------------------------------------------------------------------------
// Kernel 1: zero the scratch accumulator + probe edge_index dtype.
// int64 little-endian with values < 2^31 => every odd 32-bit word zero;
// random int32 indices can't produce 32 consecutive zeros there.
// ---------------------------------------------------------------------------
__global__ void zero_probe_kernel(int n4, const int* __restrict__ ei32) {
    int i = blockIdx.x * blockDim.x + threadIdx.x;
    if (i < n4) {
        reinterpret_cast<float4*>(g_buf)[i] = make_float4(0.f, 0.f, 0.f, 0.f);
    }
    if (blockIdx.x == 0 && threadIdx.x == 0) {
        int is64 = 1;
        #pragma unroll 1
        for (int j = 0; j < 32; j++) {
            if (ei32[2 * j + 1] != 0) { is64 = 0; break; }
        }
        g_is64 = is64;
    }
}

// ---------------------------------------------------------------------------
// Kernel 2: edge scatter.  g_buf[dst] += ||edge_attr[e]|| * x[src]
// 16 threads per edge, one float4 per thread; leader loads metadata.
// ---------------------------------------------------------------------------
__global__ void __launch_bounds__(256) edge_scatter_kernel(
    const float* __restrict__ x,
    const void* __restrict__ ei_raw,
    const float* __restrict__ ea,
    int E, int N)
{
    int t = blockIdx.x * blockDim.x + threadIdx.x;
    int e = t >> 4;
    if (e >= E) return;
    int lane = threadIdx.x & 15;
    int grpleader = threadIdx.x & 16;

    int src = 0, dst = 0;
    float scale = 0.f;
    if (lane == 0) {
        if (g_is64) {
            const long long* ei = (const long long*)ei_raw;
            src = (int)__ldg(&ei[e]);
            dst = (int)__ldg(&ei[E + e]);
        } else {
            const int* ei = (const int*)ei_raw;
            src = __ldg(&ei[e]);
            dst = __ldg(&ei[E + e]);
        }
        float a0 = __ldg(&ea[3 * e + 0]);
        float a1 = __ldg(&ea[3 * e + 1]);
        float a2 = __ldg(&ea[3 * e + 2]);
        scale = sqrtf(a0 * a0 + a1 * a1 + a2 * a2);
    }
    src   = __shfl_sync(0xffffffffu, src,   grpleader);
    dst   = __shfl_sync(0xffffffffu, dst,   grpleader);
    scale = __shfl_sync(0xffffffffu, scale, grpleader);

    if ((unsigned)src >= (unsigned)N || (unsigned)dst >= (unsigned)N) return;

    float4 v = __ldg(reinterpret_cast<const float4*>(x + (size_t)src * CH) + lane);
    v.x *= scale; v.y *= scale; v.z *= scale; v.w *= scale;

    float* addr = g_buf + (size_t)dst * CH + lane * 4;
    asm volatile("red.global.add.v4.f32 [%0], {%1, %2, %3, %4};"
                 :: "l"(addr), "f"(v.x), "f"(v.y), "f"(v.z), "f"(v.w)
                 : "memory");
}

// ---------------------------------------------------------------------------
// Kernel 3: fused GEMM   out = [x | g_buf] @ [psi ; phi]^T
// Tile: 128 nodes x 64 outputs x K=128. 256 threads.
// Per thread: 4 CONSECUTIVE nodes (nb=4*tn) x 8 outputs -> 32 accumulators.
// Per k-step: 1 aligned LDS.128 (A, conflict-free) + 2 warp-uniform LDS.128
// (W, broadcast) + 32 FFMA.
// ---------------------------------------------------------------------------
extern __shared__ float smem[];

__global__ void __launch_bounds__(256, 2) fused_gemm_kernel(
    const float* __restrict__ x,
    const float* __restrict__ phi,
    const float* __restrict__ psi,
    float* __restrict__ out,
    int N)
{
    float* As = smem;                 // As[k * ASTR + n]
    float* Ws = smem + KS * ASTR;     // Ws[k * WSTR + o]
    int tid = threadIdx.x;
    int node0 = blockIdx.x * NPB;

    // Stage W: Ws[k][o] = [psi;phi][o][k]. o fast across lanes -> STS banks
    // lane+const (conflict-free). Global: 4B per lane at 256B stride (L2-hit).
    for (int idx = tid; idx < CH * KS; idx += 256) {
        int o = idx & 63;
        int i = idx >> 6;
        float v = (i < CH) ? __ldg(&psi[o * CH + i])
                           : __ldg(&phi[o * CH + (i - CH)]);
        Ws[i * WSTR + o] = v;
    }

    // Stage A transpose: n fast across lanes -> each of the 4 STS has banks
    // lane+const (conflict-free). Global: 16B per lane at 256B stride.
    for (int idx4 = tid; idx4 < NPB * 32; idx4 += 256) {
        int n  = idx4 & 127;       // node within tile (lane-consecutive)
        int i4 = idx4 >> 7;        // which float4 of the 128-float concat row
        int gn = node0 + n;
        float4 v = make_float4(0.f, 0.f, 0.f, 0.f);
        if (gn < N) {
            v = (i4 < 16)
                ? __ldg(reinterpret_cast<const float4*>(x + (size_t)gn * CH) + i4)
                : __ldg(reinterpret_cast<const float4*>(g_buf + (size_t)gn * CH) + (i4 - 16));
        }
        int i = i4 * 4;
        As[(i + 0) * ASTR + n] = v.x;
        As[(i + 1) * ASTR + n] = v.y;
        As[(i + 2) * ASTR + n] = v.z;
        As[(i + 3) * ASTR + n] = v.w;
    }
    __syncthreads();

    int tn = tid & 31;          // lane
    int nb = tn * 4;            // 4 consecutive nodes
    int ob = (tid >> 5) * 8;    // 8 consecutive outputs (warp-uniform)

    float acc[4][8];
    #pragma unroll
    for (int j = 0; j < 4; j++)
        #pragma unroll
        for (int o = 0; o < 8; o++) acc[j][o] = 0.f;

    #pragma unroll 4
    for (int k = 0; k < KS; k++) {
        float4 a4 = *reinterpret_cast<const float4*>(As + k * ASTR + nb);
        const float4* wr = reinterpret_cast<const float4*>(Ws + k * WSTR + ob);
        float4 w0 = wr[0];
        float4 w1 = wr[1];
        float a[4] = {a4.x, a4.y, a4.z, a4.w};
        float w[8] = {w0.x, w0.y, w0.z, w0.w, w1.x, w1.y, w1.z, w1.w};
        #pragma unroll
        for (int j = 0; j < 4; j++)
            #pragma unroll
            for (int o = 0; o < 8; o++)
                acc[j][o] += a[j] * w[o];
    }

    // Output: 4 consecutive node rows x 8 floats -> 2 STG.128 each; warp
    // covers an 8KB contiguous block.
    #pragma unroll
    for (int j = 0; j < 4; j++) {
        int gn = node0 + nb + j;
        if (gn < N) {
            float4* orow = reinterpret_cast<float4*>(out + (size_t)gn * CH + ob);
            orow[0] = make_float4(acc[j][0], acc[j][1], acc[j][2], acc[j][3]);
            orow[1] = make_float4(acc[j][4], acc[j][5], acc[j][6], acc[j][7]);
        }
    }
}

// ---------------------------------------------------------------------------
// Launch
// ---------------------------------------------------------------------------
extern "C" void kernel_launch(void* const* d_in, const int* in_sizes, int n_in,
                              void* d_out, int out_size) {
    const float* x   = (const float*)d_in[0];
    const void*  ei  = d_in[1];
    const float* ea  = (const float*)d_in[2];
    const float* phi = (const float*)d_in[3];
    const float* psi = (const float*)d_in[4];
    float*       out = (float*)d_out;

    int N = in_sizes[0] / CH;   // 50000
    int E = in_sizes[1] / 2;    // 800000

    // 1. zero accumulator + probe dtype
    int n4 = (N * CH) / 4;
    zero_probe_kernel<<<(n4 + 255) / 256, 256>>>(n4, (const int*)ei);

    // 2. edge scatter (16 threads per edge)
    long long tot = (long long)E * 16;
    int eblocks = (int)((tot + 255) / 256);
    edge_scatter_kernel<<<eblocks, 256>>>(x, ei, ea, E, N);

    // 3. fused GEMM: out = [x | g_buf] @ [psi ; phi]^T
    cudaFuncSetAttribute(fused_gemm_kernel,
                         cudaFuncAttributeMaxDynamicSharedMemorySize,
                         GEMM_SMEM);
    fused_gemm_kernel<<<(N + NPB - 1) / NPB, 256, GEMM_SMEM>>>(x, phi, psi, out, N);
}